// round 1
// baseline (speedup 1.0000x reference)
#include <cuda_runtime.h>
#include <cuda_bf16.h>

// Problem constants
#define BATCH   4
#define CCH     256
#define FH      50
#define FW      50
#define HS      (FH*FW)          // 2500 spatial
#define NROI    1024
#define PP      7
#define NBIN    (PP*PP)          // 49
#define DIM     (CCH*NBIN)       // 12544
#define NCLS    80
#define NREG    320
#define NOUTT   (NCLS+NREG)      // 400
#define SCALE_F 0.0675f

// GEMM config
#define BM 64
#define BN 64
#define BKK 16
#define SPLITK 4
#define KC (DIM/SPLITK)          // 3136, divisible by 16 (3136/16=196)

// Scratch (device globals: no allocation allowed)
__device__ float g_nhwc[BATCH*HS*CCH];        // 2.56M floats, 10.2MB
__device__ float g_flat[NROI*DIM];            // 12.85M floats, 51.4MB
__device__ float g_part[SPLITK*NROI*NOUTT];   // 1.64M floats, 6.6MB

// ---------------------------------------------------------------------------
// 1) NCHW -> NHWC transpose (features), tiled through shared memory
// ---------------------------------------------------------------------------
__global__ __launch_bounds__(256) void transpose_kernel(const float* __restrict__ in) {
    __shared__ float tile[32][33];
    int b  = blockIdx.z;
    int c0 = blockIdx.y * 32;
    int s0 = blockIdx.x * 32;
    int tx = threadIdx.x;      // 0..31
    int ty = threadIdx.y;      // 0..7
#pragma unroll
    for (int i = 0; i < 4; i++) {
        int c = c0 + ty + i*8;
        int s = s0 + tx;
        float v = 0.0f;
        if (s < HS) v = in[(b*CCH + c)*HS + s];
        tile[ty + i*8][tx] = v;
    }
    __syncthreads();
#pragma unroll
    for (int i = 0; i < 4; i++) {
        int s = s0 + ty + i*8;
        int c = c0 + tx;
        if (s < HS) g_nhwc[(b*HS + s)*CCH + c] = tile[tx][ty + i*8];
    }
}

// ---------------------------------------------------------------------------
// 2) RoIAlign: one block per roi, thread = channel. Stage the roi's 12544-
//    float flat row in smem (stride-49 writes are bank-conflict-free since
//    49 mod 32 = 17 is odd), then one coalesced burst to g_flat.
// ---------------------------------------------------------------------------
__device__ __forceinline__ void corner_calc(float coord, int limit,
                                            int& lo, int& hi,
                                            float& l, float& h, int& valid) {
    valid = (coord > -1.0f) && (coord < (float)limit);
    float c = fmaxf(coord, 0.0f);
    int low = (int)floorf(c);
    if (low > limit - 1) low = limit - 1;
    int high = low + 1;
    if (high > limit - 1) high = limit - 1;
    if (low >= limit - 1) c = (float)low;
    l = c - (float)low;
    h = 1.0f - l;
    lo = low; hi = high;
}

__global__ __launch_bounds__(256) void roialign_kernel(const float* __restrict__ rois,
                                                       const int* __restrict__ ridx) {
    extern __shared__ float sflat[];           // DIM floats (50176 B)
    __shared__ int   s_yl[14], s_yh[14], s_xl[14], s_xh[14];
    __shared__ float s_ly[14], s_hy[14], s_lx[14], s_hx[14];
    __shared__ int   s_vy[14], s_vx[14];

    int n = blockIdx.x;
    int t = threadIdx.x;          // channel

    float x1 = rois[n*4+0], y1 = rois[n*4+1];
    float x2 = rois[n*4+2], y2 = rois[n*4+3];
    float sx = x1 * SCALE_F - 0.5f;
    float sy = y1 * SCALE_F - 0.5f;
    float bw = (x2 * SCALE_F - 0.5f - sx) * (1.0f/7.0f);
    float bh = (y2 * SCALE_F - 0.5f - sy) * (1.0f/7.0f);

    if (t < 14) {
        int p = t >> 1;
        float off = (float)p + ((t & 1) ? 0.75f : 0.25f);
        float coord = sy + off * bh;
        corner_calc(coord, FH, s_yl[t], s_yh[t], s_ly[t], s_hy[t], s_vy[t]);
    } else if (t < 28) {
        int q = t - 14;
        int p = q >> 1;
        float off = (float)p + ((q & 1) ? 0.75f : 0.25f);
        float coord = sx + off * bw;
        corner_calc(coord, FW, s_xl[q], s_xh[q], s_lx[q], s_hx[q], s_vx[q]);
    }
    __syncthreads();

    int b = ridx[n];
    const float* fb = g_nhwc + (size_t)b * (HS*CCH);

    for (int py = 0; py < PP; ++py) {
        for (int px = 0; px < PP; ++px) {
            float acc = 0.0f;
#pragma unroll
            for (int gy = 0; gy < 2; ++gy) {
                int i = py*2 + gy;
                if (!s_vy[i]) continue;
                const float* r0 = fb + s_yl[i]*(FW*CCH);
                const float* r1 = fb + s_yh[i]*(FW*CCH);
                float why = s_hy[i], wly = s_ly[i];
#pragma unroll
                for (int gx = 0; gx < 2; ++gx) {
                    int j = px*2 + gx;
                    if (!s_vx[j]) continue;
                    int cl = s_xl[j]*CCH + t;
                    int ch = s_xh[j]*CCH + t;
                    float whx = s_hx[j], wlx = s_lx[j];
                    acc += why * (whx * r0[cl] + wlx * r0[ch])
                         + wly * (whx * r1[cl] + wlx * r1[ch]);
                }
            }
            sflat[t*NBIN + py*PP + px] = acc * 0.25f;
        }
    }
    __syncthreads();

    float* dst = g_flat + (size_t)n * DIM;
    for (int k = t; k < DIM; k += 256) dst[k] = sflat[k];
}

// ---------------------------------------------------------------------------
// 3) GEMM: part[s][m][o] = sum over K-chunk s of flat[m][k] * w[o][k]
//    M=1024, N=400 (padded to 448), K=12544, split-K=4 for SM fill.
// ---------------------------------------------------------------------------
__global__ __launch_bounds__(256) void gemm_kernel(const float* __restrict__ Wc,
                                                   const float* __restrict__ Wr) {
    __shared__ float As[BKK][BM];
    __shared__ float Bs[BKK][BN];

    int tid = threadIdx.x;
    int m0  = blockIdx.y * BM;
    int o0  = blockIdx.x * BN;
    int kz  = blockIdx.z;
    int kbase = kz * KC;

    int lrow = tid >> 2;            // 0..63
    int lk4  = (tid & 3) * 4;       // 0,4,8,12

    const float* Arow = g_flat + (size_t)(m0 + lrow) * DIM;
    int oglob = o0 + lrow;
    const float* Brow = nullptr;
    bool bvalid = (oglob < NOUTT);
    if (bvalid) Brow = (oglob < NCLS) ? (Wc + (size_t)oglob * DIM)
                                      : (Wr + (size_t)(oglob - NCLS) * DIM);

    int tx = tid & 15, ty = tid >> 4;
    int mfrag = ty * 4, nfrag = tx * 4;

    float acc[4][4] = {};

    for (int kt = 0; kt < KC; kt += BKK) {
        int kg = kbase + kt;
        float4 av = *reinterpret_cast<const float4*>(Arow + kg + lk4);
        float4 bv = make_float4(0.f, 0.f, 0.f, 0.f);
        if (bvalid) bv = *reinterpret_cast<const float4*>(Brow + kg + lk4);

        __syncthreads();
        As[lk4+0][lrow] = av.x; As[lk4+1][lrow] = av.y;
        As[lk4+2][lrow] = av.z; As[lk4+3][lrow] = av.w;
        Bs[lk4+0][lrow] = bv.x; Bs[lk4+1][lrow] = bv.y;
        Bs[lk4+2][lrow] = bv.z; Bs[lk4+3][lrow] = bv.w;
        __syncthreads();

#pragma unroll
        for (int k = 0; k < BKK; k++) {
            float4 a4 = *reinterpret_cast<const float4*>(&As[k][mfrag]);
            float4 b4 = *reinterpret_cast<const float4*>(&Bs[k][nfrag]);
            acc[0][0] += a4.x*b4.x; acc[0][1] += a4.x*b4.y; acc[0][2] += a4.x*b4.z; acc[0][3] += a4.x*b4.w;
            acc[1][0] += a4.y*b4.x; acc[1][1] += a4.y*b4.y; acc[1][2] += a4.y*b4.z; acc[1][3] += a4.y*b4.w;
            acc[2][0] += a4.z*b4.x; acc[2][1] += a4.z*b4.y; acc[2][2] += a4.z*b4.z; acc[2][3] += a4.z*b4.w;
            acc[3][0] += a4.w*b4.x; acc[3][1] += a4.w*b4.y; acc[3][2] += a4.w*b4.z; acc[3][3] += a4.w*b4.w;
        }
    }

#pragma unroll
    for (int i = 0; i < 4; i++) {
        int m = m0 + mfrag + i;
#pragma unroll
        for (int j = 0; j < 4; j++) {
            int o = o0 + nfrag + j;
            if (o < NOUTT) g_part[((size_t)kz*NROI + m)*NOUTT + o] = acc[i][j];
        }
    }
}

// ---------------------------------------------------------------------------
// 4) Split-K reduce + bias + scatter into harness output layout
//    out = [cls (1024x80)] ++ [reg (1024x320)]
// ---------------------------------------------------------------------------
__global__ __launch_bounds__(256) void reduce_kernel(const float* __restrict__ bcls,
                                                     const float* __restrict__ breg,
                                                     float* __restrict__ out) {
    int idx = blockIdx.x * blockDim.x + threadIdx.x;
    if (idx >= NROI * NOUTT) return;
    int n = idx / NOUTT;
    int o = idx - n * NOUTT;
    float v = 0.0f;
#pragma unroll
    for (int s = 0; s < SPLITK; s++) v += g_part[((size_t)s*NROI + n)*NOUTT + o];
    if (o < NCLS) {
        out[(size_t)n*NCLS + o] = v + bcls[o];
    } else {
        out[(size_t)NROI*NCLS + (size_t)n*NREG + (o - NCLS)] = v + breg[o - NCLS];
    }
}

// ---------------------------------------------------------------------------
extern "C" void kernel_launch(void* const* d_in, const int* in_sizes, int n_in,
                              void* d_out, int out_size) {
    const float* features = (const float*)d_in[0];
    const float* rois     = (const float*)d_in[1];
    const int*   ridx     = (const int*)  d_in[2];
    const float* w_cls    = (const float*)d_in[3];
    const float* b_cls    = (const float*)d_in[4];
    const float* w_reg    = (const float*)d_in[5];
    const float* b_reg    = (const float*)d_in[6];
    float* out = (float*)d_out;

    static bool attr_set = false;
    if (!attr_set) {
        cudaFuncSetAttribute(roialign_kernel,
                             cudaFuncAttributeMaxDynamicSharedMemorySize,
                             DIM * (int)sizeof(float));
        attr_set = true;
    }

    // 1) NCHW -> NHWC
    {
        dim3 grid((HS + 31) / 32, CCH / 32, BATCH);
        dim3 block(32, 8);
        transpose_kernel<<<grid, block>>>(features);
    }
    // 2) RoIAlign -> g_flat
    roialign_kernel<<<NROI, 256, DIM * sizeof(float)>>>(rois, ridx);
    // 3) GEMM (split-K partials)
    {
        dim3 grid((NOUTT + BN - 1) / BN, NROI / BM, SPLITK);  // 7 x 16 x 4
        gemm_kernel<<<grid, 256>>>(w_cls, w_reg);
    }
    // 4) Reduce + bias + scatter
    reduce_kernel<<<(NROI*NOUTT + 255) / 256, 256>>>(b_cls, b_reg, out);
}

// round 4
// speedup vs baseline: 2.0286x; 2.0286x over previous
#include <cuda_runtime.h>
#include <cuda_bf16.h>
#include <cstdint>

// Problem constants
#define BATCH   4
#define CCH     256
#define FH      50
#define FW      50
#define HS      (FH*FW)          // 2500
#define NROI    1024
#define PP      7
#define NBIN    (PP*PP)          // 49
#define DIM     (CCH*NBIN)       // 12544
#define NCLS    80
#define NREG    320
#define NOUTT   (NCLS+NREG)      // 400
#define NPAD    448              // 7 * 64
#define SCALE_F 0.0675f

// GEMM config (mma.sync bf16, base sm_100-compatible)
#define TM      128
#define TN      64
#define BK      32
#define SPLITK  4
#define KC      (DIM/SPLITK)     // 3136
#define NSTEP   (KC/BK)          // 98

// smem tile layout: padded pitch 40 bf16 = 80 bytes (conflict-free ldmatrix)
#define PITCHB  80
#define A_BYTES (TM*PITCHB)      // 10240
#define B_BYTES (TN*PITCHB)      // 5120
#define O_AHI   0
#define O_ALO   (A_BYTES)        // 10240
#define O_BHI   (2*A_BYTES)      // 20480
#define O_BLO   (2*A_BYTES + B_BYTES) // 25600
#define STG_BYTES (2*A_BYTES + 2*B_BYTES) // 30720
#define SMEM_GEMM (2*STG_BYTES)  // 61440

// Scratch (device globals — allocation is forbidden)
__device__ float         g_nhwc[BATCH*HS*CCH];
__device__ __nv_bfloat16 g_ahi[(size_t)NROI*DIM];
__device__ __nv_bfloat16 g_alo[(size_t)NROI*DIM];
__device__ __nv_bfloat16 g_bhi[(size_t)NPAD*DIM];
__device__ __nv_bfloat16 g_blo[(size_t)NPAD*DIM];
__device__ float         g_part[(size_t)SPLITK*NROI*NOUTT]; // [s][m][o]

// ---------------------------------------------------------------------------
// PTX helpers (sm_80-era instructions only)
// ---------------------------------------------------------------------------
__device__ __forceinline__ uint32_t smem_u32(const void* p) {
    uint32_t a;
    asm("{ .reg .u64 t; cvta.to.shared.u64 t, %1; cvt.u32.u64 %0, t; }"
        : "=r"(a) : "l"(p));
    return a;
}
__device__ __forceinline__ void cpa16(uint32_t d, const void* s) {
    asm volatile("cp.async.cg.shared.global [%0], [%1], 16;" :: "r"(d), "l"(s));
}
__device__ __forceinline__ void ldsm4(uint32_t* r, uint32_t a) {
    asm volatile("ldmatrix.sync.aligned.m8n8.x4.shared.b16 {%0,%1,%2,%3}, [%4];"
                 : "=r"(r[0]), "=r"(r[1]), "=r"(r[2]), "=r"(r[3]) : "r"(a));
}
__device__ __forceinline__ void mma16816(float* c, const uint32_t* a, const uint32_t* b) {
    asm volatile(
        "mma.sync.aligned.m16n8k16.row.col.f32.bf16.bf16.f32 "
        "{%0,%1,%2,%3}, {%4,%5,%6,%7}, {%8,%9}, {%0,%1,%2,%3};"
        : "+f"(c[0]), "+f"(c[1]), "+f"(c[2]), "+f"(c[3])
        : "r"(a[0]), "r"(a[1]), "r"(a[2]), "r"(a[3]), "r"(b[0]), "r"(b[1]));
}

// ---------------------------------------------------------------------------
// 1) NCHW -> NHWC transpose
// ---------------------------------------------------------------------------
__global__ __launch_bounds__(256) void transpose_kernel(const float* __restrict__ in) {
    __shared__ float tile[32][33];
    int b  = blockIdx.z;
    int c0 = blockIdx.y * 32;
    int s0 = blockIdx.x * 32;
    int tx = threadIdx.x, ty = threadIdx.y;
#pragma unroll
    for (int i = 0; i < 4; i++) {
        int c = c0 + ty + i*8, s = s0 + tx;
        float v = 0.0f;
        if (s < HS) v = in[(b*CCH + c)*HS + s];
        tile[ty + i*8][tx] = v;
    }
    __syncthreads();
#pragma unroll
    for (int i = 0; i < 4; i++) {
        int s = s0 + ty + i*8, c = c0 + tx;
        if (s < HS) g_nhwc[(b*HS + s)*CCH + c] = tile[tx][ty + i*8];
    }
}

// ---------------------------------------------------------------------------
// 2) Weight split: W -> (hi, lo) bf16, padded to NPAD rows
// ---------------------------------------------------------------------------
__global__ __launch_bounds__(256) void wsplit_kernel(const float* __restrict__ Wc,
                                                     const float* __restrict__ Wr) {
    int k = blockIdx.x * 256 + threadIdx.x;   // 0..12543
    int o = blockIdx.y;                       // 0..447
    float v = 0.0f;
    if (o < NCLS)       v = Wc[(size_t)o * DIM + k];
    else if (o < NOUTT) v = Wr[(size_t)(o - NCLS) * DIM + k];
    __nv_bfloat16 h = __float2bfloat16(v);
    __nv_bfloat16 l = __float2bfloat16(v - __bfloat162float(h));
    g_bhi[(size_t)o * DIM + k] = h;
    g_blo[(size_t)o * DIM + k] = l;
}

// ---------------------------------------------------------------------------
// 3) RoIAlign -> hi/lo bf16 flat rows
// ---------------------------------------------------------------------------
__device__ __forceinline__ void corner_calc(float coord, int limit,
                                            int& lo, int& hi,
                                            float& l, float& h, int& valid) {
    valid = (coord > -1.0f) && (coord < (float)limit);
    float c = fmaxf(coord, 0.0f);
    int low = (int)floorf(c);
    if (low > limit - 1) low = limit - 1;
    int high = low + 1;
    if (high > limit - 1) high = limit - 1;
    if (low >= limit - 1) c = (float)low;
    l = c - (float)low;
    h = 1.0f - l;
    lo = low; hi = high;
}

__global__ __launch_bounds__(256) void roialign_kernel(const float* __restrict__ rois,
                                                       const int* __restrict__ ridx) {
    extern __shared__ float sflat[];          // DIM floats
    __shared__ int   s_yl[14], s_yh[14], s_xl[14], s_xh[14];
    __shared__ float s_ly[14], s_hy[14], s_lx[14], s_hx[14];
    __shared__ int   s_vy[14], s_vx[14];

    int n = blockIdx.x;
    int t = threadIdx.x;

    float x1 = rois[n*4+0], y1 = rois[n*4+1];
    float x2 = rois[n*4+2], y2 = rois[n*4+3];
    float sx = x1 * SCALE_F - 0.5f;
    float sy = y1 * SCALE_F - 0.5f;
    float bw = (x2 * SCALE_F - 0.5f - sx) * (1.0f/7.0f);
    float bh = (y2 * SCALE_F - 0.5f - sy) * (1.0f/7.0f);

    if (t < 14) {
        int p = t >> 1;
        float off = (float)p + ((t & 1) ? 0.75f : 0.25f);
        corner_calc(sy + off * bh, FH, s_yl[t], s_yh[t], s_ly[t], s_hy[t], s_vy[t]);
    } else if (t < 28) {
        int q = t - 14;
        int p = q >> 1;
        float off = (float)p + ((q & 1) ? 0.75f : 0.25f);
        corner_calc(sx + off * bw, FW, s_xl[q], s_xh[q], s_lx[q], s_hx[q], s_vx[q]);
    }
    __syncthreads();

    int b = ridx[n];
    const float* fb = g_nhwc + (size_t)b * (HS*CCH);

    for (int py = 0; py < PP; ++py) {
        for (int px = 0; px < PP; ++px) {
            float acc = 0.0f;
#pragma unroll
            for (int gy = 0; gy < 2; ++gy) {
                int i = py*2 + gy;
                if (!s_vy[i]) continue;
                const float* r0 = fb + s_yl[i]*(FW*CCH);
                const float* r1 = fb + s_yh[i]*(FW*CCH);
                float why = s_hy[i], wly = s_ly[i];
#pragma unroll
                for (int gx = 0; gx < 2; ++gx) {
                    int j = px*2 + gx;
                    if (!s_vx[j]) continue;
                    int cl = s_xl[j]*CCH + t;
                    int ch = s_xh[j]*CCH + t;
                    float whx = s_hx[j], wlx = s_lx[j];
                    acc += why * (whx * r0[cl] + wlx * r0[ch])
                         + wly * (whx * r1[cl] + wlx * r1[ch]);
                }
            }
            sflat[t*NBIN + py*PP + px] = acc * 0.25f;
        }
    }
    __syncthreads();

    __nv_bfloat16* dh = g_ahi + (size_t)n * DIM;
    __nv_bfloat16* dl = g_alo + (size_t)n * DIM;
    for (int k = t; k < DIM; k += 256) {
        float v = sflat[k];
        __nv_bfloat16 h = __float2bfloat16(v);
        dh[k] = h;
        dl[k] = __float2bfloat16(v - __bfloat162float(h));
    }
}

// ---------------------------------------------------------------------------
// 4) mma.sync bf16 GEMM with error compensation.
//    D[128x64] fp32 += Ahi*Bhi + Ahi*Blo + Alo*Bhi over K-chunk.
//    grid = (7 N-tiles, 8 M-tiles, 4 K-splits); partials -> g_part[s][m][o]
// ---------------------------------------------------------------------------
__global__ __launch_bounds__(256) void gemm_mma_kernel() {
    extern __shared__ char smem[];
    uint32_t sb = smem_u32(smem);
    int t = threadIdx.x;
    int lane = t & 31, wid = t >> 5;

    int o0 = blockIdx.x * TN;
    int m0 = blockIdx.y * TM;
    int kz = blockIdx.z;
    int kbase = kz * KC;

    const size_t ROWB = (size_t)DIM * 2;
    const char* gah = (const char*)g_ahi + ((size_t)m0 * DIM + kbase) * 2;
    const char* gal = (const char*)g_alo + ((size_t)m0 * DIM + kbase) * 2;
    const char* gbh = (const char*)g_bhi + ((size_t)o0 * DIM + kbase) * 2;
    const char* gbl = (const char*)g_blo + ((size_t)o0 * DIM + kbase) * 2;

    // per-stage loader: A = 128x32 bf16 (hi+lo), B = 64x32 bf16 (hi+lo)
    auto load_stage = [&](int step, int st) {
        size_t kb = (size_t)step * (BK * 2);           // 64 bytes per step
        uint32_t base = sb + st * STG_BYTES;
        // A: 512 chunks of 16B, 2 per thread (hi & lo)
#pragma unroll
        for (int i = 0; i < 2; i++) {
            int u = i * 256 + t;
            int r = u >> 2, c = u & 3;
            uint32_t doff = r * PITCHB + c * 16;
            size_t   soff = (size_t)r * ROWB + kb + c * 16;
            cpa16(base + O_AHI + doff, gah + soff);
            cpa16(base + O_ALO + doff, gal + soff);
        }
        // B: 256 chunks of 16B, 1 per thread (hi & lo)
        {
            int r = t >> 2, c = t & 3;
            uint32_t doff = r * PITCHB + c * 16;
            size_t   soff = (size_t)r * ROWB + kb + c * 16;
            cpa16(base + O_BHI + doff, gbh + soff);
            cpa16(base + O_BLO + doff, gbl + soff);
        }
        asm volatile("cp.async.commit_group;" ::: "memory");
    };

    // warp tiling: 4 (M) x 2 (N) warps; warp tile 32x32
    int wm = wid >> 1, wn = wid & 1;
    int mbase = wm * 32, nbase = wn * 32;

    // ldmatrix lane address components
    int aRow = lane & 15;            // A row within m16
    int aK   = (lane >> 4) * 8;      // A k-offset (elems)
    int bN   = ((lane >> 4) << 3) + (lane & 7);   // B n within 16
    int bK   = ((lane >> 3) & 1) * 8;             // B k-offset (elems)

    uint32_t aoff[2], boff[2];
#pragma unroll
    for (int mt = 0; mt < 2; mt++)
        aoff[mt] = (uint32_t)((mbase + mt*16 + aRow) * PITCHB + aK * 2);
#pragma unroll
    for (int j = 0; j < 2; j++)
        boff[j] = (uint32_t)((nbase + j*16 + bN) * PITCHB + bK * 2);

    float acc[2][4][4];
#pragma unroll
    for (int mt = 0; mt < 2; mt++)
#pragma unroll
        for (int nt = 0; nt < 4; nt++)
#pragma unroll
            for (int e = 0; e < 4; e++) acc[mt][nt][e] = 0.0f;

    load_stage(0, 0);

    for (int i = 0; i < NSTEP; i++) {
        int cur = i & 1;
        if (i + 1 < NSTEP) {
            load_stage(i + 1, cur ^ 1);
            asm volatile("cp.async.wait_group 1;" ::: "memory");
        } else {
            asm volatile("cp.async.wait_group 0;" ::: "memory");
        }
        __syncthreads();

        uint32_t base = sb + cur * STG_BYTES;
#pragma unroll
        for (int ks = 0; ks < 2; ks++) {
            uint32_t kso = ks * 32;   // 16 bf16 = 32 bytes
            uint32_t ah[2][4], al[2][4];
#pragma unroll
            for (int mt = 0; mt < 2; mt++) {
                ldsm4(ah[mt], base + O_AHI + aoff[mt] + kso);
                ldsm4(al[mt], base + O_ALO + aoff[mt] + kso);
            }
            uint32_t bh[8], bl[8];
            ldsm4(bh,     base + O_BHI + boff[0] + kso);
            ldsm4(bh + 4, base + O_BHI + boff[1] + kso);
            ldsm4(bl,     base + O_BLO + boff[0] + kso);
            ldsm4(bl + 4, base + O_BLO + boff[1] + kso);
#pragma unroll
            for (int mt = 0; mt < 2; mt++)
#pragma unroll
                for (int nt = 0; nt < 4; nt++)
                    mma16816(acc[mt][nt], ah[mt], &bh[nt*2]);
#pragma unroll
            for (int mt = 0; mt < 2; mt++)
#pragma unroll
                for (int nt = 0; nt < 4; nt++)
                    mma16816(acc[mt][nt], ah[mt], &bl[nt*2]);
#pragma unroll
            for (int mt = 0; mt < 2; mt++)
#pragma unroll
                for (int nt = 0; nt < 4; nt++)
                    mma16816(acc[mt][nt], al[mt], &bh[nt*2]);
        }
        __syncthreads();
    }

    // Epilogue: c0,c1 -> (row, col..col+1); c2,c3 -> (row+8, col..col+1)
    int r  = lane >> 2;
    int cq = (lane & 3) * 2;
    float* gp = g_part + (size_t)kz * NROI * NOUTT;
#pragma unroll
    for (int mt = 0; mt < 2; mt++) {
        int m = m0 + mbase + mt*16 + r;
#pragma unroll
        for (int nt = 0; nt < 4; nt++) {
            int o = o0 + nbase + nt*8 + cq;
            if (o < NOUTT) {
                *(float2*)(gp + (size_t)m * NOUTT + o) =
                    make_float2(acc[mt][nt][0], acc[mt][nt][1]);
                *(float2*)(gp + (size_t)(m + 8) * NOUTT + o) =
                    make_float2(acc[mt][nt][2], acc[mt][nt][3]);
            }
        }
    }
}

// ---------------------------------------------------------------------------
// 5) Split-K reduce + bias + scatter (out = [cls 1024x80][reg 1024x320])
// ---------------------------------------------------------------------------
__global__ __launch_bounds__(256) void reduce_kernel(const float* __restrict__ bcls,
                                                     const float* __restrict__ breg,
                                                     float* __restrict__ out) {
    int idx = blockIdx.x * blockDim.x + threadIdx.x;
    if (idx >= NROI * NOUTT) return;
    int n = idx / NOUTT;
    int o = idx - n * NOUTT;
    float v = 0.0f;
#pragma unroll
    for (int s = 0; s < SPLITK; s++)
        v += g_part[((size_t)s * NROI + n) * NOUTT + o];
    if (o < NCLS) out[(size_t)n * NCLS + o] = v + bcls[o];
    else          out[(size_t)NROI * NCLS + (size_t)n * NREG + (o - NCLS)] = v + breg[o - NCLS];
}

// ---------------------------------------------------------------------------
extern "C" void kernel_launch(void* const* d_in, const int* in_sizes, int n_in,
                              void* d_out, int out_size) {
    const float* features = (const float*)d_in[0];
    const float* rois     = (const float*)d_in[1];
    const int*   ridx     = (const int*)  d_in[2];
    const float* w_cls    = (const float*)d_in[3];
    const float* b_cls    = (const float*)d_in[4];
    const float* w_reg    = (const float*)d_in[5];
    const float* b_reg    = (const float*)d_in[6];
    float* out = (float*)d_out;

    static bool attr_set = false;
    if (!attr_set) {
        cudaFuncSetAttribute(roialign_kernel,
                             cudaFuncAttributeMaxDynamicSharedMemorySize,
                             DIM * (int)sizeof(float));
        cudaFuncSetAttribute(gemm_mma_kernel,
                             cudaFuncAttributeMaxDynamicSharedMemorySize,
                             SMEM_GEMM);
        attr_set = true;
    }

    {   // 1) NCHW -> NHWC
        dim3 grid((HS + 31) / 32, CCH / 32, BATCH);
        dim3 block(32, 8);
        transpose_kernel<<<grid, block>>>(features);
    }
    {   // 2) weight split (padded)
        dim3 grid(DIM / 256, NPAD);
        wsplit_kernel<<<grid, 256>>>(w_cls, w_reg);
    }
    // 3) RoIAlign -> hi/lo bf16 flat
    roialign_kernel<<<NROI, 256, DIM * sizeof(float)>>>(rois, ridx);
    {   // 4) tensor-core GEMM partials
        dim3 grid(NPAD / TN, NROI / TM, SPLITK);   // 7 x 8 x 4
        gemm_mma_kernel<<<grid, 256, SMEM_GEMM>>>();
    }
    // 5) reduce + bias + scatter
    reduce_kernel<<<(NROI * NOUTT + 255) / 256, 256>>>(b_cls, b_reg, out);
}

// round 5
// speedup vs baseline: 2.4688x; 1.2170x over previous
#include <cuda_runtime.h>
#include <cuda_bf16.h>
#include <cstdint>

// Problem constants
#define BATCH   4
#define CCH     256
#define FH      50
#define FW      50
#define HS      (FH*FW)          // 2500
#define NROI    1024
#define PP      7
#define NBIN    (PP*PP)          // 49
#define DIM     (CCH*NBIN)       // 12544
#define NCLS    80
#define NREG    320
#define NOUTT   (NCLS+NREG)      // 400
#define NPAD    448              // 7 * 64
#define SCALE_F 0.0675f

// GEMM config (mma.sync bf16, base sm_100-compatible)
#define TM      128
#define TN      64
#define BK      32
#define SPLITK  4
#define KC      (DIM/SPLITK)     // 3136
#define NSTEP   (KC/BK)          // 98
#define NSTAGE  3

// smem tile layout: padded pitch 40 bf16 = 80 bytes (conflict-free ldmatrix)
#define PITCHB  80
#define A_BYTES (TM*PITCHB)      // 10240
#define B_BYTES (TN*PITCHB)      // 5120
#define O_AHI   0
#define O_ALO   (A_BYTES)        // 10240
#define O_BHI   (2*A_BYTES)      // 20480
#define O_BLO   (2*A_BYTES + B_BYTES) // 25600
#define STG_BYTES (2*A_BYTES + 2*B_BYTES) // 30720
#define SMEM_GEMM (NSTAGE*STG_BYTES)      // 92160

// Scratch (device globals — allocation is forbidden)
// NOTE: flat k-index is PERMUTED: k = bin*256 + c (consistent for A and B).
__device__ float         g_nhwc[BATCH*HS*CCH];
__device__ __nv_bfloat16 g_ahi[(size_t)NROI*DIM];
__device__ __nv_bfloat16 g_alo[(size_t)NROI*DIM];
__device__ __nv_bfloat16 g_bhi[(size_t)NPAD*DIM];
__device__ __nv_bfloat16 g_blo[(size_t)NPAD*DIM];
__device__ float         g_part[(size_t)SPLITK*NROI*NOUTT]; // [s][m][o]

// ---------------------------------------------------------------------------
// PTX helpers (sm_80-era instructions only)
// ---------------------------------------------------------------------------
__device__ __forceinline__ uint32_t smem_u32(const void* p) {
    uint32_t a;
    asm("{ .reg .u64 t; cvta.to.shared.u64 t, %1; cvt.u32.u64 %0, t; }"
        : "=r"(a) : "l"(p));
    return a;
}
__device__ __forceinline__ void cpa16(uint32_t d, const void* s) {
    asm volatile("cp.async.cg.shared.global [%0], [%1], 16;" :: "r"(d), "l"(s));
}
__device__ __forceinline__ void ldsm4(uint32_t* r, uint32_t a) {
    asm volatile("ldmatrix.sync.aligned.m8n8.x4.shared.b16 {%0,%1,%2,%3}, [%4];"
                 : "=r"(r[0]), "=r"(r[1]), "=r"(r[2]), "=r"(r[3]) : "r"(a));
}
__device__ __forceinline__ void mma16816(float* c, const uint32_t* a, const uint32_t* b) {
    asm volatile(
        "mma.sync.aligned.m16n8k16.row.col.f32.bf16.bf16.f32 "
        "{%0,%1,%2,%3}, {%4,%5,%6,%7}, {%8,%9}, {%0,%1,%2,%3};"
        : "+f"(c[0]), "+f"(c[1]), "+f"(c[2]), "+f"(c[3])
        : "r"(a[0]), "r"(a[1]), "r"(a[2]), "r"(a[3]), "r"(b[0]), "r"(b[1]));
}

// ---------------------------------------------------------------------------
// 1) NCHW -> NHWC transpose
// ---------------------------------------------------------------------------
__global__ __launch_bounds__(256) void transpose_kernel(const float* __restrict__ in) {
    __shared__ float tile[32][33];
    int b  = blockIdx.z;
    int c0 = blockIdx.y * 32;
    int s0 = blockIdx.x * 32;
    int tx = threadIdx.x, ty = threadIdx.y;
#pragma unroll
    for (int i = 0; i < 4; i++) {
        int c = c0 + ty + i*8, s = s0 + tx;
        float v = 0.0f;
        if (s < HS) v = in[(b*CCH + c)*HS + s];
        tile[ty + i*8][tx] = v;
    }
    __syncthreads();
#pragma unroll
    for (int i = 0; i < 4; i++) {
        int s = s0 + ty + i*8, c = c0 + tx;
        if (s < HS) g_nhwc[(b*HS + s)*CCH + c] = tile[tx][ty + i*8];
    }
}

// ---------------------------------------------------------------------------
// 2) Weight split + k-permutation: W[o][c*49+bin] -> (hi,lo)[o][bin*256+c]
//    One block per padded output row; row staged in smem so both gmem read
//    and write are coalesced (smem stride-49 reads are conflict-free).
// ---------------------------------------------------------------------------
__global__ __launch_bounds__(256) void wsplit_kernel(const float* __restrict__ Wc,
                                                     const float* __restrict__ Wr) {
    extern __shared__ float srow[];       // DIM floats
    int o = blockIdx.x, t = threadIdx.x;
    const float* src = nullptr;
    if (o < NCLS)       src = Wc + (size_t)o * DIM;
    else if (o < NOUTT) src = Wr + (size_t)(o - NCLS) * DIM;
    for (int k = t; k < DIM; k += 256) srow[k] = src ? src[k] : 0.0f;
    __syncthreads();
    __nv_bfloat16* dh = g_bhi + (size_t)o * DIM;
    __nv_bfloat16* dl = g_blo + (size_t)o * DIM;
    for (int kn = t; kn < DIM; kn += 256) {
        int bin = kn >> 8, c = kn & 255;
        float v = srow[c * NBIN + bin];
        __nv_bfloat16 h = __float2bfloat16(v);
        dh[kn] = h;
        dl[kn] = __float2bfloat16(v - __bfloat162float(h));
    }
}

// ---------------------------------------------------------------------------
// 3) RoIAlign: grid (NROI, 7). Block handles one py row of bins; thread =
//    channel. With the permuted k layout the 2-byte writes per bin are fully
//    coalesced — no smem staging, tiny footprint, high occupancy.
// ---------------------------------------------------------------------------
__device__ __forceinline__ void corner_calc(float coord, int limit,
                                            int& lo, int& hi,
                                            float& l, float& h, int& valid) {
    valid = (coord > -1.0f) && (coord < (float)limit);
    float c = fmaxf(coord, 0.0f);
    int low = (int)floorf(c);
    if (low > limit - 1) low = limit - 1;
    int high = low + 1;
    if (high > limit - 1) high = limit - 1;
    if (low >= limit - 1) c = (float)low;
    l = c - (float)low;
    h = 1.0f - l;
    lo = low; hi = high;
}

__global__ __launch_bounds__(256) void roialign_kernel(const float* __restrict__ rois,
                                                       const int* __restrict__ ridx) {
    __shared__ int   s_xl[14], s_xh[14], s_vx[14];
    __shared__ float s_lx[14], s_hx[14];
    __shared__ int   s_yl[2], s_yh[2], s_vy[2];
    __shared__ float s_ly[2], s_hy[2];

    int n  = blockIdx.x;
    int py = blockIdx.y;
    int t  = threadIdx.x;

    float x1 = rois[n*4+0], y1 = rois[n*4+1];
    float x2 = rois[n*4+2], y2 = rois[n*4+3];
    float sx = x1 * SCALE_F - 0.5f;
    float sy = y1 * SCALE_F - 0.5f;
    float bw = (x2 * SCALE_F - 0.5f - sx) * (1.0f/7.0f);
    float bh = (y2 * SCALE_F - 0.5f - sy) * (1.0f/7.0f);

    if (t < 14) {
        int p = t >> 1;
        float off = (float)p + ((t & 1) ? 0.75f : 0.25f);
        corner_calc(sx + off * bw, FW, s_xl[t], s_xh[t], s_lx[t], s_hx[t], s_vx[t]);
    } else if (t < 16) {
        int gy = t - 14;
        float off = (float)py + (gy ? 0.75f : 0.25f);
        corner_calc(sy + off * bh, FH, s_yl[gy], s_yh[gy], s_ly[gy], s_hy[gy], s_vy[gy]);
    }
    __syncthreads();

    int b = ridx[n];
    const float* fb = g_nhwc + (size_t)b * (HS*CCH);

    const float* r0a = fb + s_yl[0]*(FW*CCH);
    const float* r1a = fb + s_yh[0]*(FW*CCH);
    const float* r0b = fb + s_yl[1]*(FW*CCH);
    const float* r1b = fb + s_yh[1]*(FW*CCH);
    float hy0 = s_hy[0], ly0 = s_ly[0], hy1 = s_hy[1], ly1 = s_ly[1];
    int   vy0 = s_vy[0], vy1 = s_vy[1];

    __nv_bfloat16* dh = g_ahi + (size_t)n * DIM;
    __nv_bfloat16* dl = g_alo + (size_t)n * DIM;

#pragma unroll
    for (int px = 0; px < PP; ++px) {
        float acc = 0.0f;
#pragma unroll
        for (int gx = 0; gx < 2; ++gx) {
            int j = px*2 + gx;
            if (!s_vx[j]) continue;
            int cl = s_xl[j]*CCH + t;
            int ch = s_xh[j]*CCH + t;
            float whx = s_hx[j], wlx = s_lx[j];
            if (vy0) acc += hy0 * (whx * r0a[cl] + wlx * r0a[ch])
                          + ly0 * (whx * r1a[cl] + wlx * r1a[ch]);
            if (vy1) acc += hy1 * (whx * r0b[cl] + wlx * r0b[ch])
                          + ly1 * (whx * r1b[cl] + wlx * r1b[ch]);
        }
        acc *= 0.25f;
        int bin = py * PP + px;
        __nv_bfloat16 h = __float2bfloat16(acc);
        dh[bin*256 + t] = h;
        dl[bin*256 + t] = __float2bfloat16(acc - __bfloat162float(h));
    }
}

// ---------------------------------------------------------------------------
// 4) mma.sync bf16 GEMM, 3-stage cp.async pipeline, ONE barrier per K-step.
//    D[128x64] fp32 += Ahi*Bhi + Ahi*Blo + Alo*Bhi over K-chunk.
// ---------------------------------------------------------------------------
__global__ __launch_bounds__(256) void gemm_mma_kernel() {
    extern __shared__ char smem[];
    uint32_t sb = smem_u32(smem);
    int t = threadIdx.x;
    int lane = t & 31, wid = t >> 5;

    int o0 = blockIdx.x * TN;
    int m0 = blockIdx.y * TM;
    int kz = blockIdx.z;
    int kbase = kz * KC;

    const size_t ROWB = (size_t)DIM * 2;
    const char* gah = (const char*)g_ahi + ((size_t)m0 * DIM + kbase) * 2;
    const char* gal = (const char*)g_alo + ((size_t)m0 * DIM + kbase) * 2;
    const char* gbh = (const char*)g_bhi + ((size_t)o0 * DIM + kbase) * 2;
    const char* gbl = (const char*)g_blo + ((size_t)o0 * DIM + kbase) * 2;

    auto load_stage = [&](int step, int st) {
        size_t kb = (size_t)step * (BK * 2);           // 64 bytes per step
        uint32_t base = sb + st * STG_BYTES;
#pragma unroll
        for (int i = 0; i < 2; i++) {
            int u = i * 256 + t;
            int r = u >> 2, c = u & 3;
            uint32_t doff = r * PITCHB + c * 16;
            size_t   soff = (size_t)r * ROWB + kb + c * 16;
            cpa16(base + O_AHI + doff, gah + soff);
            cpa16(base + O_ALO + doff, gal + soff);
        }
        {
            int r = t >> 2, c = t & 3;
            uint32_t doff = r * PITCHB + c * 16;
            size_t   soff = (size_t)r * ROWB + kb + c * 16;
            cpa16(base + O_BHI + doff, gbh + soff);
            cpa16(base + O_BLO + doff, gbl + soff);
        }
        asm volatile("cp.async.commit_group;" ::: "memory");
    };

    int wm = wid >> 1, wn = wid & 1;
    int mbase = wm * 32, nbase = wn * 32;

    int aRow = lane & 15;
    int aK   = (lane >> 4) * 8;
    int bN   = ((lane >> 4) << 3) + (lane & 7);
    int bK   = ((lane >> 3) & 1) * 8;

    uint32_t aoff[2], boff[2];
#pragma unroll
    for (int mt = 0; mt < 2; mt++)
        aoff[mt] = (uint32_t)((mbase + mt*16 + aRow) * PITCHB + aK * 2);
#pragma unroll
    for (int j = 0; j < 2; j++)
        boff[j] = (uint32_t)((nbase + j*16 + bN) * PITCHB + bK * 2);

    float acc[2][4][4];
#pragma unroll
    for (int mt = 0; mt < 2; mt++)
#pragma unroll
        for (int nt = 0; nt < 4; nt++)
#pragma unroll
            for (int e = 0; e < 4; e++) acc[mt][nt][e] = 0.0f;

    load_stage(0, 0);
    load_stage(1, 1);

    int stage = 0;
    for (int i = 0; i < NSTEP; i++) {
        if (i + 2 < NSTEP) {
            asm volatile("cp.async.wait_group 1;" ::: "memory");
        } else {
            asm volatile("cp.async.wait_group 0;" ::: "memory");
        }
        __syncthreads();
        // prefetch step i+2 into the stage mma(i-1) finished with
        if (i + 2 < NSTEP) {
            int nst = stage + 2; if (nst >= NSTAGE) nst -= NSTAGE;
            load_stage(i + 2, nst);
        }

        uint32_t base = sb + stage * STG_BYTES;
#pragma unroll
        for (int ks = 0; ks < 2; ks++) {
            uint32_t kso = ks * 32;
            uint32_t ah[2][4], al[2][4];
#pragma unroll
            for (int mt = 0; mt < 2; mt++) {
                ldsm4(ah[mt], base + O_AHI + aoff[mt] + kso);
                ldsm4(al[mt], base + O_ALO + aoff[mt] + kso);
            }
            uint32_t bh[8], bl[8];
            ldsm4(bh,     base + O_BHI + boff[0] + kso);
            ldsm4(bh + 4, base + O_BHI + boff[1] + kso);
            ldsm4(bl,     base + O_BLO + boff[0] + kso);
            ldsm4(bl + 4, base + O_BLO + boff[1] + kso);
#pragma unroll
            for (int mt = 0; mt < 2; mt++)
#pragma unroll
                for (int nt = 0; nt < 4; nt++)
                    mma16816(acc[mt][nt], ah[mt], &bh[nt*2]);
#pragma unroll
            for (int mt = 0; mt < 2; mt++)
#pragma unroll
                for (int nt = 0; nt < 4; nt++)
                    mma16816(acc[mt][nt], ah[mt], &bl[nt*2]);
#pragma unroll
            for (int mt = 0; mt < 2; mt++)
#pragma unroll
                for (int nt = 0; nt < 4; nt++)
                    mma16816(acc[mt][nt], al[mt], &bh[nt*2]);
        }
        stage++; if (stage >= NSTAGE) stage = 0;
    }

    int r  = lane >> 2;
    int cq = (lane & 3) * 2;
    float* gp = g_part + (size_t)kz * NROI * NOUTT;
#pragma unroll
    for (int mt = 0; mt < 2; mt++) {
        int m = m0 + mbase + mt*16 + r;
#pragma unroll
        for (int nt = 0; nt < 4; nt++) {
            int o = o0 + nbase + nt*8 + cq;
            if (o < NOUTT) {
                *(float2*)(gp + (size_t)m * NOUTT + o) =
                    make_float2(acc[mt][nt][0], acc[mt][nt][1]);
                *(float2*)(gp + (size_t)(m + 8) * NOUTT + o) =
                    make_float2(acc[mt][nt][2], acc[mt][nt][3]);
            }
        }
    }
}

// ---------------------------------------------------------------------------
// 5) Split-K reduce + bias + scatter (out = [cls 1024x80][reg 1024x320])
// ---------------------------------------------------------------------------
__global__ __launch_bounds__(256) void reduce_kernel(const float* __restrict__ bcls,
                                                     const float* __restrict__ breg,
                                                     float* __restrict__ out) {
    int idx = blockIdx.x * blockDim.x + threadIdx.x;
    if (idx >= NROI * NOUTT) return;
    int n = idx / NOUTT;
    int o = idx - n * NOUTT;
    float v = 0.0f;
#pragma unroll
    for (int s = 0; s < SPLITK; s++)
        v += g_part[((size_t)s * NROI + n) * NOUTT + o];
    if (o < NCLS) out[(size_t)n * NCLS + o] = v + bcls[o];
    else          out[(size_t)NROI * NCLS + (size_t)n * NREG + (o - NCLS)] = v + breg[o - NCLS];
}

// ---------------------------------------------------------------------------
extern "C" void kernel_launch(void* const* d_in, const int* in_sizes, int n_in,
                              void* d_out, int out_size) {
    const float* features = (const float*)d_in[0];
    const float* rois     = (const float*)d_in[1];
    const int*   ridx     = (const int*)  d_in[2];
    const float* w_cls    = (const float*)d_in[3];
    const float* b_cls    = (const float*)d_in[4];
    const float* w_reg    = (const float*)d_in[5];
    const float* b_reg    = (const float*)d_in[6];
    float* out = (float*)d_out;

    static bool attr_set = false;
    if (!attr_set) {
        cudaFuncSetAttribute(wsplit_kernel,
                             cudaFuncAttributeMaxDynamicSharedMemorySize,
                             DIM * (int)sizeof(float));
        cudaFuncSetAttribute(gemm_mma_kernel,
                             cudaFuncAttributeMaxDynamicSharedMemorySize,
                             SMEM_GEMM);
        attr_set = true;
    }

    {   // 1) NCHW -> NHWC
        dim3 grid((HS + 31) / 32, CCH / 32, BATCH);
        dim3 block(32, 8);
        transpose_kernel<<<grid, block>>>(features);
    }
    // 2) weight split + permute (padded)
    wsplit_kernel<<<NPAD, 256, DIM * sizeof(float)>>>(w_cls, w_reg);
    // 3) RoIAlign -> hi/lo bf16 flat (permuted k), 7 blocks per roi
    {
        dim3 grid(NROI, PP);
        roialign_kernel<<<grid, 256>>>(rois, ridx);
    }
    {   // 4) tensor-core GEMM partials
        dim3 grid(NPAD / TN, NROI / TM, SPLITK);   // 7 x 8 x 4
        gemm_mma_kernel<<<grid, 256, SMEM_GEMM>>>();
    }
    // 5) reduce + bias + scatter
    reduce_kernel<<<(NROI * NOUTT + 255) / 256, 256>>>(b_cls, b_reg, out);
}